// round 7
// baseline (speedup 1.0000x reference)
#include <cuda_runtime.h>

#define NT    256      // threads per block
#define LSEQ  8192     // sequence length
#define KB    8        // kernels per group
#define CIN   12       // input channels
#define CPER  6        // gathered channels per group
#define NG    32       // groups
#define NDIL  10       // dilations

// packed f32x2 helpers (sm_100+; ptxas never auto-fuses these)
union F2 { float2 f; unsigned long long u; };

__device__ __forceinline__ void ffma2(F2& d, const F2& a, const F2& b, const F2& c) {
    asm("fma.rn.f32x2 %0, %1, %2, %3;" : "=l"(d.u) : "l"(a.u), "l"(b.u), "l"(c.u));
}
__device__ __forceinline__ void fmul2(F2& d, const F2& a, const F2& b) {
    asm("mul.rn.f32x2 %0, %1, %2;" : "=l"(d.u) : "l"(a.u), "l"(b.u));
}
__device__ __forceinline__ void fadd2(F2& d, const F2& a, const F2& b) {
    asm("add.rn.f32x2 %0, %1, %2;" : "=l"(d.u) : "l"(a.u), "l"(b.u));
}

// Block = one (b, di, j, g). Input staged DUPLICATED in shared: slot s holds
// (v, v) so LDS.64 broadcasts a tap into both f32x2 halves with no MOV.
// 9-tap dilated conv, 8 kernels k-packed in f32x2; max/min FMNMX trees;
// histogram via equality-predicated register accumulators; shuffle reduce.
template<int D>
__global__ __launch_bounds__(NT) void hydra_kernel(
    const float* __restrict__ X,   // (32, 12, 8192)
    const float* __restrict__ W,   // (10, 2, 256, 1, 9)
    const int*   __restrict__ I,   // (10, 2, 32, 6)
    float* __restrict__ out,       // (32, 1280, 8)
    int di)
{
    extern __shared__ float smem[];
    float*  wsh  = smem;                         // 72 floats, transposed [tap][k]
    float2* inp2 = (float2*)(smem + 72);         // (S+1) duplicated slots

    const int g   = blockIdx.x;
    const int jj  = blockIdx.y;                  // 0 = X branch, 1 = diff branch
    const int b   = blockIdx.z;
    const int tid = threadIdx.x;

    const int dj = di * 2 + jj;
    const int S  = LSEQ + 8 * D;                 // slot s <-> t = s - 4D

    // ---- weights to shared, transposed so (k,k+1) pairs are adjacent ----
    if (tid < KB * 9) {
        int k = tid / 9, i = tid % 9;
        wsh[i * 8 + k] = W[((dj * NG + g) * KB + k) * 9 + i];
    }

    // ---- gather indices ----
    int idx[CPER];
#pragma unroll
    for (int c = 0; c < CPER; c++)
        idx[c] = I[(dj * NG + g) * CPER + c] * LSEQ;

    const float* Xb = X + (size_t)b * CIN * LSEQ;

    // ---- zero the halo slots (these are exactly the out-of-range zeros) ----
    for (int s = tid; s < 4 * D; s += NT)
        inp2[s] = make_float2(0.f, 0.f);
    for (int s = 4 * D + LSEQ + tid; s < S + 1; s += NT)
        inp2[s] = make_float2(0.f, 0.f);

    // ---- vectorized gather-sum staging: float4 loads, f32x2 adds, dup stores ----
#pragma unroll
    for (int it = 0; it < LSEQ / (NT * 4); it++) {   // exactly 8 iterations
        const int u0 = (tid + it * NT) * 4;          // 16B-aligned (idx mult of LSEQ)
        F2 lo, hi;
        {
            float4 v = *reinterpret_cast<const float4*>(Xb + idx[0] + u0);
            lo.f = make_float2(v.x, v.y);
            hi.f = make_float2(v.z, v.w);
        }
#pragma unroll
        for (int c = 1; c < CPER; c++) {
            float4 v = *reinterpret_cast<const float4*>(Xb + idx[c] + u0);
            F2 a, b2;
            a.f  = make_float2(v.x, v.y);
            b2.f = make_float2(v.z, v.w);
            fadd2(lo, lo, a);
            fadd2(hi, hi, b2);
        }
        const int sb = 4 * D + u0;
        inp2[sb]     = make_float2(lo.f.x, lo.f.x);
        inp2[sb + 1] = make_float2(lo.f.y, lo.f.y);
        inp2[sb + 2] = make_float2(hi.f.x, hi.f.x);
        inp2[sb + 3] = make_float2(hi.f.y, hi.f.y);
    }
    __syncthreads();

    // ---- diff branch: in-place chunked diff on duplicated slots ----
    if (jj == 1) {
        for (int base = 0; base < S; base += NT) {
            int s = base + tid;
            float dv = 0.f;
            if (s < S) {
                int t = s - 4 * D;
                float a  = inp2[s].x;
                float b2 = inp2[s + 1].x;
                if (t >= 0 && t < LSEQ - 1) dv = b2 - a;
            }
            __syncthreads();
            if (s < S) inp2[s] = make_float2(dv, dv);
            __syncthreads();
        }
    }

    // ---- weights to packed registers: w2[i][kp] = (w[2kp][i], w[2kp+1][i]) ----
    F2 w2[9][4];
#pragma unroll
    for (int i = 0; i < 9; i++)
#pragma unroll
        for (int kp = 0; kp < 4; kp++)
            w2[i][kp].f = *reinterpret_cast<const float2*>(&wsh[i * 8 + kp * 2]);

    float cmax[KB], cmin[KB];
#pragma unroll
    for (int k = 0; k < KB; k++) { cmax[k] = 0.f; cmin[k] = 0.f; }

    const int Lj = LSEQ - jj;                    // 8192 or 8191

    // ---- main loop: 32 iterations, LDS.64 taps land pre-broadcast ----
#pragma unroll 2
    for (int it = 0; it < LSEQ / NT; it++) {
        const int t = tid + it * NT;
        const float2* ip = inp2 + t;

        F2 z[4], xx;
        xx.f = ip[0];
#pragma unroll
        for (int kp = 0; kp < 4; kp++) fmul2(z[kp], w2[0][kp], xx);
#pragma unroll
        for (int i = 1; i < 9; i++) {
            xx.f = ip[i * D];                    // LDS.64 with immediate offset
#pragma unroll
            for (int kp = 0; kp < 4; kp++) ffma2(z[kp], w2[i][kp], xx, z[kp]);
        }

        float m0 = fmaxf(z[0].f.x, z[0].f.y);
        float m1 = fmaxf(z[1].f.x, z[1].f.y);
        float m2 = fmaxf(z[2].f.x, z[2].f.y);
        float m3 = fmaxf(z[3].f.x, z[3].f.y);
        float maxv = fmaxf(fmaxf(m0, m1), fmaxf(m2, m3));
        float n0 = fminf(z[0].f.x, z[0].f.y);
        float n1 = fminf(z[1].f.x, z[1].f.y);
        float n2 = fminf(z[2].f.x, z[2].f.y);
        float n3 = fminf(z[3].f.x, z[3].f.y);
        float minv = fminf(fminf(n0, n1), fminf(n2, n3));

        if (t < Lj) {
#pragma unroll
            for (int kp = 0; kp < 4; kp++) {
                float zl = z[kp].f.x, zh = z[kp].f.y;
                if (zl == maxv) cmax[2 * kp]     += zl;
                if (zh == maxv) cmax[2 * kp + 1] += zh;
                if (zl == minv) cmin[2 * kp]     += 1.f;
                if (zh == minv) cmin[2 * kp + 1] += 1.f;
            }
        }
    }

    // ---- warp shuffle reduction of 16 accumulators ----
#pragma unroll
    for (int off = 16; off > 0; off >>= 1) {
#pragma unroll
        for (int k = 0; k < KB; k++) {
            cmax[k] += __shfl_down_sync(0xffffffffu, cmax[k], off);
            cmin[k] += __shfl_down_sync(0xffffffffu, cmin[k], off);
        }
    }

    __syncthreads();                             // inp reads done; reuse as scratch
    float* red = (float*)inp2;                   // red[q*8 + warp], q in [0,16)
    const int warp = tid >> 5;
    if ((tid & 31) == 0) {
#pragma unroll
        for (int k = 0; k < KB; k++) {
            red[k * 8 + warp]       = cmax[k];
            red[(8 + k) * 8 + warp] = cmin[k];
        }
    }
    __syncthreads();

    if (tid < 16) {
        float v = 0.f;
#pragma unroll
        for (int w = 0; w < 8; w++) v += red[tid * 8 + w];
        v = fmaxf(v, 0.f);
        int which = tid >> 3;                    // 0 = cmax, 1 = cmin
        int k     = tid & 7;
        size_t ch = (size_t)((di * 4 + jj * 2 + which) * NG + g);
        out[((size_t)b * (4 * NDIL * NG) + ch) * KB + k] = v;
    }
}

template<int D>
static void launch_one(const float* X, const float* W, const int* I,
                       float* out, int di) {
    int smem = 72 * (int)sizeof(float) + (LSEQ + 8 * D + 1) * (int)sizeof(float2);
    cudaFuncSetAttribute(hydra_kernel<D>,
                         cudaFuncAttributeMaxDynamicSharedMemorySize, smem);
    dim3 grid(NG, 2, 32);                        // (g, j, b)
    hydra_kernel<D><<<grid, NT, smem>>>(X, W, I, out, di);
}

extern "C" void kernel_launch(void* const* d_in, const int* in_sizes, int n_in,
                              void* d_out, int out_size) {
    const float* X = (const float*)d_in[0];
    const float* W = (const float*)d_in[1];
    const int*   I = (const int*)d_in[2];
    float* out = (float*)d_out;

    launch_one<1>(X, W, I, out, 0);
    launch_one<2>(X, W, I, out, 1);
    launch_one<4>(X, W, I, out, 2);
    launch_one<8>(X, W, I, out, 3);
    launch_one<16>(X, W, I, out, 4);
    launch_one<32>(X, W, I, out, 5);
    launch_one<64>(X, W, I, out, 6);
    launch_one<128>(X, W, I, out, 7);
    launch_one<256>(X, W, I, out, 8);
    launch_one<512>(X, W, I, out, 9);
}

// round 8
// speedup vs baseline: 1.0558x; 1.0558x over previous
#include <cuda_runtime.h>

#define NT    256      // threads per block
#define LSEQ  8192     // sequence length
#define KB    8        // kernels per group
#define CIN   12       // input channels
#define CPER  6        // gathered channels per group
#define NG    32       // groups
#define NDIL  10       // dilations

// packed f32x2 helpers (sm_100+; ptxas never auto-fuses these)
union F2 { float2 f; unsigned long long u; };

__device__ __forceinline__ void ffma2(F2& d, const F2& a, const F2& b, const F2& c) {
    asm("fma.rn.f32x2 %0, %1, %2, %3;" : "=l"(d.u) : "l"(a.u), "l"(b.u), "l"(c.u));
}
__device__ __forceinline__ void fmul2(F2& d, const F2& a, const F2& b) {
    asm("mul.rn.f32x2 %0, %1, %2;" : "=l"(d.u) : "l"(a.u), "l"(b.u));
}
__device__ __forceinline__ void fadd2(F2& d, const F2& a, const F2& b) {
    asm("add.rn.f32x2 %0, %1, %2;" : "=l"(d.u) : "l"(a.u), "l"(b.u));
}

// Block = one (b, di, j, g). Input staged DUPLICATED in shared: slot s holds
// (v, v) so LDS.64 broadcasts a tap into both f32x2 halves with no MOV.
// 9-tap dilated conv, 8 kernels k-packed in f32x2; max/min FMNMX trees;
// histogram via equality-predicated register accumulators; shuffle reduce.
template<int D>
__global__ __launch_bounds__(NT) void hydra_kernel(
    const float* __restrict__ X,   // (32, 12, 8192)
    const float* __restrict__ W,   // (10, 2, 256, 1, 9)
    const int*   __restrict__ I,   // (10, 2, 32, 6)
    float* __restrict__ out,       // (32, 1280, 8)
    int di)
{
    extern __shared__ float smem[];
    float*  wsh  = smem;                         // 72 floats, transposed [tap][k]
    float2* inp2 = (float2*)(smem + 72);         // (S+1) duplicated slots

    const int g   = blockIdx.x;
    const int jj  = blockIdx.y;                  // 0 = X branch, 1 = diff branch
    const int b   = blockIdx.z;
    const int tid = threadIdx.x;

    const int dj = di * 2 + jj;
    const int S  = LSEQ + 8 * D;                 // slot s <-> t = s - 4D

    // ---- weights to shared, transposed so (k,k+1) pairs are adjacent ----
    if (tid < KB * 9) {
        int k = tid / 9, i = tid % 9;
        wsh[i * 8 + k] = W[((dj * NG + g) * KB + k) * 9 + i];
    }

    // ---- gather indices ----
    int idx[CPER];
#pragma unroll
    for (int c = 0; c < CPER; c++)
        idx[c] = I[(dj * NG + g) * CPER + c] * LSEQ;

    const float* Xb = X + (size_t)b * CIN * LSEQ;

    // ---- zero the halo slots (these are exactly the out-of-range zeros) ----
    for (int s = tid; s < 4 * D; s += NT)
        inp2[s] = make_float2(0.f, 0.f);
    for (int s = 4 * D + LSEQ + tid; s < S + 1; s += NT)
        inp2[s] = make_float2(0.f, 0.f);

    // ---- vectorized gather-sum staging: float4 loads, f32x2 adds, dup stores ----
#pragma unroll
    for (int it = 0; it < LSEQ / (NT * 4); it++) {   // exactly 8 iterations
        const int u0 = (tid + it * NT) * 4;          // 16B-aligned (idx mult of LSEQ)
        F2 lo, hi;
        {
            float4 v = *reinterpret_cast<const float4*>(Xb + idx[0] + u0);
            lo.f = make_float2(v.x, v.y);
            hi.f = make_float2(v.z, v.w);
        }
#pragma unroll
        for (int c = 1; c < CPER; c++) {
            float4 v = *reinterpret_cast<const float4*>(Xb + idx[c] + u0);
            F2 a, b2;
            a.f  = make_float2(v.x, v.y);
            b2.f = make_float2(v.z, v.w);
            fadd2(lo, lo, a);
            fadd2(hi, hi, b2);
        }
        const int sb = 4 * D + u0;
        inp2[sb]     = make_float2(lo.f.x, lo.f.x);
        inp2[sb + 1] = make_float2(lo.f.y, lo.f.y);
        inp2[sb + 2] = make_float2(hi.f.x, hi.f.x);
        inp2[sb + 3] = make_float2(hi.f.y, hi.f.y);
    }
    __syncthreads();

    // ---- diff branch: in-place chunked diff on duplicated slots ----
    if (jj == 1) {
        for (int base = 0; base < S; base += NT) {
            int s = base + tid;
            float dv = 0.f;
            if (s < S) {
                int t = s - 4 * D;
                float a  = inp2[s].x;
                float b2 = inp2[s + 1].x;
                if (t >= 0 && t < LSEQ - 1) dv = b2 - a;
            }
            __syncthreads();
            if (s < S) inp2[s] = make_float2(dv, dv);
            __syncthreads();
        }
    }

    // ---- weights to packed registers: w2[i][kp] = (w[2kp][i], w[2kp+1][i]) ----
    F2 w2[9][4];
#pragma unroll
    for (int i = 0; i < 9; i++)
#pragma unroll
        for (int kp = 0; kp < 4; kp++)
            w2[i][kp].f = *reinterpret_cast<const float2*>(&wsh[i * 8 + kp * 2]);

    float cmax[KB], cmin[KB];
#pragma unroll
    for (int k = 0; k < KB; k++) { cmax[k] = 0.f; cmin[k] = 0.f; }

    const int Lj = LSEQ - jj;                    // 8192 or 8191

    // ---- main loop: 32 iterations, LDS.64 taps land pre-broadcast ----
#pragma unroll 2
    for (int it = 0; it < LSEQ / NT; it++) {
        const int t = tid + it * NT;
        const float2* ip = inp2 + t;

        F2 z[4], xx;
        xx.f = ip[0];
#pragma unroll
        for (int kp = 0; kp < 4; kp++) fmul2(z[kp], w2[0][kp], xx);
#pragma unroll
        for (int i = 1; i < 9; i++) {
            xx.f = ip[i * D];                    // LDS.64 with immediate offset
#pragma unroll
            for (int kp = 0; kp < 4; kp++) ffma2(z[kp], w2[i][kp], xx, z[kp]);
        }

        float m0 = fmaxf(z[0].f.x, z[0].f.y);
        float m1 = fmaxf(z[1].f.x, z[1].f.y);
        float m2 = fmaxf(z[2].f.x, z[2].f.y);
        float m3 = fmaxf(z[3].f.x, z[3].f.y);
        float maxv = fmaxf(fmaxf(m0, m1), fmaxf(m2, m3));
        float n0 = fminf(z[0].f.x, z[0].f.y);
        float n1 = fminf(z[1].f.x, z[1].f.y);
        float n2 = fminf(z[2].f.x, z[2].f.y);
        float n3 = fminf(z[3].f.x, z[3].f.y);
        float minv = fminf(fminf(n0, n1), fminf(n2, n3));

        if (t < Lj) {
#pragma unroll
            for (int kp = 0; kp < 4; kp++) {
                float zl = z[kp].f.x, zh = z[kp].f.y;
                if (zl == maxv) cmax[2 * kp]     += zl;
                if (zh == maxv) cmax[2 * kp + 1] += zh;
                if (zl == minv) cmin[2 * kp]     += 1.f;
                if (zh == minv) cmin[2 * kp + 1] += 1.f;
            }
        }
    }

    // ---- warp shuffle reduction of 16 accumulators ----
#pragma unroll
    for (int off = 16; off > 0; off >>= 1) {
#pragma unroll
        for (int k = 0; k < KB; k++) {
            cmax[k] += __shfl_down_sync(0xffffffffu, cmax[k], off);
            cmin[k] += __shfl_down_sync(0xffffffffu, cmin[k], off);
        }
    }

    __syncthreads();                             // inp reads done; reuse as scratch
    float* red = (float*)inp2;                   // red[q*8 + warp], q in [0,16)
    const int warp = tid >> 5;
    if ((tid & 31) == 0) {
#pragma unroll
        for (int k = 0; k < KB; k++) {
            red[k * 8 + warp]       = cmax[k];
            red[(8 + k) * 8 + warp] = cmin[k];
        }
    }
    __syncthreads();

    if (tid < 16) {
        float v = 0.f;
#pragma unroll
        for (int w = 0; w < 8; w++) v += red[tid * 8 + w];
        v = fmaxf(v, 0.f);
        int which = tid >> 3;                    // 0 = cmax, 1 = cmin
        int k     = tid & 7;
        size_t ch = (size_t)((di * 4 + jj * 2 + which) * NG + g);
        out[((size_t)b * (4 * NDIL * NG) + ch) * KB + k] = v;
    }
}

template<int D>
static void launch_one(const float* X, const float* W, const int* I,
                       float* out, int di) {
    int smem = 72 * (int)sizeof(float) + (LSEQ + 8 * D + 1) * (int)sizeof(float2);
    cudaFuncSetAttribute(hydra_kernel<D>,
                         cudaFuncAttributeMaxDynamicSharedMemorySize, smem);
    dim3 grid(NG, 2, 32);                        // (g, j, b)
    hydra_kernel<D><<<grid, NT, smem>>>(X, W, I, out, di);
}

extern "C" void kernel_launch(void* const* d_in, const int* in_sizes, int n_in,
                              void* d_out, int out_size) {
    const float* X = (const float*)d_in[0];
    const float* W = (const float*)d_in[1];
    const int*   I = (const int*)d_in[2];
    float* out = (float*)d_out;

    launch_one<1>(X, W, I, out, 0);
    launch_one<2>(X, W, I, out, 1);
    launch_one<4>(X, W, I, out, 2);
    launch_one<8>(X, W, I, out, 3);
    launch_one<16>(X, W, I, out, 4);
    launch_one<32>(X, W, I, out, 5);
    launch_one<64>(X, W, I, out, 6);
    launch_one<128>(X, W, I, out, 7);
    launch_one<256>(X, W, I, out, 8);
    launch_one<512>(X, W, I, out, 9);
}